// round 2
// baseline (speedup 1.0000x reference)
#include <cuda_runtime.h>
#include <cuda_bf16.h>
#include <math.h>

// Problem constants
#define Bn 2
#define Sn 2048
#define Dn 1024
#define Hn 16
#define DKn 64
#define FDn 64
#define Mrows (Bn*Sn)     // 4096

// ---------------- scratch (no allocs allowed) ----------------
__device__ float g_Q[Mrows * Dn];
__device__ float g_K[Mrows * Dn];
__device__ float g_V[Mrows * Dn];
__device__ float g_A[Mrows * Dn];
__device__ float g_Fn[Bn * Sn * FDn];
__device__ float g_Rn[Bn * Sn * FDn];

// ---------------- l2 normalize (warp per row of 64) ----------------
__global__ __launch_bounds__(256) void l2norm_kernel(
    const float* __restrict__ feat, const float* __restrict__ req,
    float* __restrict__ featn, float* __restrict__ reqn)
{
    int warp = (blockIdx.x * blockDim.x + threadIdx.x) >> 5;
    int lane = threadIdx.x & 31;
    if (warp >= 2 * Bn * Sn) return;
    const float* src; float* dst; int row;
    if (warp < Bn * Sn) { src = feat; dst = featn; row = warp; }
    else                { src = req;  dst = reqn;  row = warp - Bn * Sn; }
    float2 v = ((const float2*)src)[row * 32 + lane];
    float ss = v.x * v.x + v.y * v.y;
    #pragma unroll
    for (int o = 16; o; o >>= 1) ss += __shfl_xor_sync(0xffffffffu, ss, o);
    float inv = 1.0f / fmaxf(sqrtf(ss), 1e-12f);
    ((float2*)dst)[row * 32 + lane] = make_float2(v.x * inv, v.y * inv);
}

// ---------------- fp32 SGEMM: C = A[4096,1024] * W[1024,1024] + bias ----------------
// 128x128 tile, BK=8, 256 threads, 8x8 microtile. gridDim.z selects (W,b,C) triple.
#define BM 128
#define BN 128
#define BKK 8
__global__ __launch_bounds__(256, 2) void sgemm3(
    const float* __restrict__ A,
    const float* __restrict__ W0, const float* __restrict__ W1, const float* __restrict__ W2,
    const float* __restrict__ b0, const float* __restrict__ b1, const float* __restrict__ b2,
    float* __restrict__ C0, float* __restrict__ C1, float* __restrict__ C2)
{
    const int Kd = Dn, Nd = Dn;
    const float* __restrict__ W    = (blockIdx.z == 0) ? W0 : (blockIdx.z == 1) ? W1 : W2;
    const float* __restrict__ bias = (blockIdx.z == 0) ? b0 : (blockIdx.z == 1) ? b1 : b2;
    float* __restrict__ C          = (blockIdx.z == 0) ? C0 : (blockIdx.z == 1) ? C1 : C2;

    __shared__ float As[BKK][BM + 4];   // transposed, padded (conflict-free stores)
    __shared__ float Bs[BKK][BN];

    int tid = threadIdx.x;
    int tx = tid & 15, ty = tid >> 4;
    int m0 = blockIdx.y * BM, n0 = blockIdx.x * BN;

    float acc[8][8];
    #pragma unroll
    for (int i = 0; i < 8; i++)
        #pragma unroll
        for (int j = 0; j < 8; j++) acc[i][j] = 0.0f;

    int arow = tid >> 1;            // 0..127
    int akq  = (tid & 1) * 4;       // 0 or 4
    int brow = tid >> 5;            // 0..7
    int bcol = (tid & 31) * 4;

    const float* Aptr = A + (size_t)(m0 + arow) * Kd + akq;
    const float* Wptr = W + (size_t)brow * Nd + n0 + bcol;

    for (int k0 = 0; k0 < Kd; k0 += BKK) {
        float4 av = *(const float4*)(Aptr + k0);
        float4 bv = *(const float4*)(Wptr + (size_t)k0 * Nd);
        As[akq + 0][arow] = av.x;
        As[akq + 1][arow] = av.y;
        As[akq + 2][arow] = av.z;
        As[akq + 3][arow] = av.w;
        *(float4*)&Bs[brow][bcol] = bv;
        __syncthreads();
        #pragma unroll
        for (int kk = 0; kk < BKK; kk++) {
            float ar[8], br[8];
            *(float4*)&ar[0] = *(const float4*)&As[kk][ty * 8];
            *(float4*)&ar[4] = *(const float4*)&As[kk][ty * 8 + 4];
            *(float4*)&br[0] = *(const float4*)&Bs[kk][tx * 8];
            *(float4*)&br[4] = *(const float4*)&Bs[kk][tx * 8 + 4];
            #pragma unroll
            for (int i = 0; i < 8; i++)
                #pragma unroll
                for (int j = 0; j < 8; j++)
                    acc[i][j] += ar[i] * br[j];
        }
        __syncthreads();
    }

    float bb[8];
    *(float4*)&bb[0] = *(const float4*)&bias[n0 + tx * 8];
    *(float4*)&bb[4] = *(const float4*)&bias[n0 + tx * 8 + 4];
    #pragma unroll
    for (int i = 0; i < 8; i++) {
        size_t row = (size_t)(m0 + ty * 8 + i);
        float4 o0 = make_float4(acc[i][0] + bb[0], acc[i][1] + bb[1],
                                acc[i][2] + bb[2], acc[i][3] + bb[3]);
        float4 o1 = make_float4(acc[i][4] + bb[4], acc[i][5] + bb[5],
                                acc[i][6] + bb[6], acc[i][7] + bb[7]);
        *(float4*)&C[row * Nd + n0 + tx * 8]     = o0;
        *(float4*)&C[row * Nd + n0 + tx * 8 + 4] = o1;
    }
}

// ---------------- flash attention with fused ASA bias ----------------
// Per block: 64 query rows x 64 key cols per iteration, 256 threads (16x16), 4x4 microtiles.
// Qext = [Q/8, req_n] (128 dims), Kext = [K, feat_n] -> S = Qext . Kext^T directly
// includes the bias term.
#define QPAD 132
#define VPAD 68
#define PPAD 65
#define QS_OFF 0
#define KS_OFF (64 * QPAD)                 // 8448
#define VS_OFF (KS_OFF + 64 * QPAD)        // 16896
#define PS_OFF (VS_OFF + 64 * VPAD)        // 21248
#define SMEM_FLOATS (PS_OFF + 64 * PPAD)   // 25408
#define SMEM_BYTES (SMEM_FLOATS * 4)       // 101632

__global__ __launch_bounds__(256) void attn_kernel(
    const float* __restrict__ Q, const float* __restrict__ K, const float* __restrict__ V,
    const float* __restrict__ featn, const float* __restrict__ reqn,
    float* __restrict__ Oout)
{
    extern __shared__ float sm[];
    float* Qs = sm + QS_OFF;
    float* Ks = sm + KS_OFF;
    float* Vs = sm + VS_OFF;
    float* Ps = sm + PS_OFF;

    int tid = threadIdx.x;
    int tx = tid & 15, ty = tid >> 4;
    int m0t = gridDim.x - 1 - blockIdx.x;    // largest tiles first
    int h = blockIdx.y, b = blockIdx.z;
    int qbase = m0t * 64;
    int browbase = b * Sn;

    // ---- load Qext tile: [64][128] (Q/8 | req_n) ----
    for (int idx = tid; idx < 64 * 32; idx += 256) {
        int r = idx >> 5;
        int d = (idx & 31) * 4;
        int grow = browbase + qbase + r;
        float4 v;
        if (d < 64) {
            v = *(const float4*)&Q[(size_t)grow * Dn + h * DKn + d];
            v.x *= 0.125f; v.y *= 0.125f; v.z *= 0.125f; v.w *= 0.125f;
        } else {
            v = *(const float4*)&reqn[(size_t)grow * FDn + (d - 64)];
        }
        *(float4*)&Qs[r * QPAD + d] = v;
    }

    float o[4][4];
    #pragma unroll
    for (int i = 0; i < 4; i++)
        #pragma unroll
        for (int j = 0; j < 4; j++) o[i][j] = 0.0f;
    float mrow[4], lrow[4];
    #pragma unroll
    for (int i = 0; i < 4; i++) { mrow[i] = -1e30f; lrow[i] = 0.0f; }

    for (int jt = 0; jt <= m0t; jt++) {
        int kbase = jt * 64;
        // ---- load Kext tile + V tile ----
        for (int idx = tid; idx < 64 * 32; idx += 256) {
            int c = idx >> 5;
            int d = (idx & 31) * 4;
            int grow = browbase + kbase + c;
            float4 v;
            if (d < 64) v = *(const float4*)&K[(size_t)grow * Dn + h * DKn + d];
            else        v = *(const float4*)&featn[(size_t)grow * FDn + (d - 64)];
            *(float4*)&Ks[c * QPAD + d] = v;
        }
        for (int idx = tid; idx < 64 * 16; idx += 256) {
            int c = idx >> 4;
            int d = (idx & 15) * 4;
            int grow = browbase + kbase + c;
            *(float4*)&Vs[c * VPAD + d] =
                *(const float4*)&V[(size_t)grow * Dn + h * DKn + d];
        }
        __syncthreads();

        // ---- S tile: s[i][j] = Qext[r] . Kext[c] ----
        float s[4][4];
        #pragma unroll
        for (int i = 0; i < 4; i++)
            #pragma unroll
            for (int j = 0; j < 4; j++) s[i][j] = 0.0f;

        #pragma unroll 8
        for (int d = 0; d < 128; d += 4) {
            float4 q[4], k[4];
            #pragma unroll
            for (int i = 0; i < 4; i++)
                q[i] = *(const float4*)&Qs[(ty * 4 + i) * QPAD + d];
            #pragma unroll
            for (int j = 0; j < 4; j++)
                k[j] = *(const float4*)&Ks[(tx * 4 + j) * QPAD + d];
            #pragma unroll
            for (int i = 0; i < 4; i++)
                #pragma unroll
                for (int j = 0; j < 4; j++)
                    s[i][j] += q[i].x * k[j].x + q[i].y * k[j].y +
                               q[i].z * k[j].z + q[i].w * k[j].w;
        }

        // ---- causal mask on diagonal tile ----
        if (jt == m0t) {
            #pragma unroll
            for (int i = 0; i < 4; i++)
                #pragma unroll
                for (int j = 0; j < 4; j++)
                    if ((tx * 4 + j) > (ty * 4 + i)) s[i][j] = -1e30f;
        }

        // ---- online softmax update (per row, reduce over 16 lanes) ----
        #pragma unroll
        for (int i = 0; i < 4; i++) {
            float tm = fmaxf(fmaxf(s[i][0], s[i][1]), fmaxf(s[i][2], s[i][3]));
            #pragma unroll
            for (int off = 1; off < 16; off <<= 1)
                tm = fmaxf(tm, __shfl_xor_sync(0xffffffffu, tm, off));
            float mnew = fmaxf(mrow[i], tm);
            float corr = __expf(mrow[i] - mnew);
            float rs = 0.0f;
            #pragma unroll
            for (int j = 0; j < 4; j++) {
                float p = __expf(s[i][j] - mnew);
                s[i][j] = p;
                rs += p;
            }
            #pragma unroll
            for (int off = 1; off < 16; off <<= 1)
                rs += __shfl_xor_sync(0xffffffffu, rs, off);
            lrow[i] = lrow[i] * corr + rs;
            mrow[i] = mnew;
            #pragma unroll
            for (int j = 0; j < 4; j++) o[i][j] *= corr;
        }

        // ---- P to smem ----
        #pragma unroll
        for (int i = 0; i < 4; i++)
            #pragma unroll
            for (int j = 0; j < 4; j++)
                Ps[(ty * 4 + i) * PPAD + tx * 4 + j] = s[i][j];
        __syncthreads();

        // ---- O += P * V ----
        #pragma unroll 8
        for (int c = 0; c < 64; c++) {
            float4 v = *(const float4*)&Vs[c * VPAD + tx * 4];
            float pc[4];
            #pragma unroll
            for (int i = 0; i < 4; i++) pc[i] = Ps[(ty * 4 + i) * PPAD + c];
            #pragma unroll
            for (int i = 0; i < 4; i++) {
                o[i][0] += pc[i] * v.x;
                o[i][1] += pc[i] * v.y;
                o[i][2] += pc[i] * v.z;
                o[i][3] += pc[i] * v.w;
            }
        }
        __syncthreads();   // protect Ks/Vs/Ps before next tile load
    }

    // ---- epilogue ----
    #pragma unroll
    for (int i = 0; i < 4; i++) {
        float inv = 1.0f / lrow[i];
        int grow = browbase + qbase + ty * 4 + i;
        float4 ov = make_float4(o[i][0] * inv, o[i][1] * inv,
                                o[i][2] * inv, o[i][3] * inv);
        *(float4*)&Oout[(size_t)grow * Dn + h * DKn + tx * 4] = ov;
    }
}

// ---------------- launch ----------------
extern "C" void kernel_launch(void* const* d_in, const int* in_sizes, int n_in,
                              void* d_out, int out_size)
{
    const float* x    = (const float*)d_in[0];
    const float* feat = (const float*)d_in[1];
    const float* req  = (const float*)d_in[2];
    const float* Wq   = (const float*)d_in[3];
    const float* bq   = (const float*)d_in[4];
    const float* Wk   = (const float*)d_in[5];
    const float* bk   = (const float*)d_in[6];
    const float* Wv   = (const float*)d_in[7];
    const float* bv   = (const float*)d_in[8];
    const float* Wo   = (const float*)d_in[9];
    const float* bo   = (const float*)d_in[10];
    // d_in[11] pos_ids, d_in[12] causal_mask: unused (mask is deterministic tril)
    float* out = (float*)d_out;

    float *gQ, *gK, *gV, *gA, *gFn, *gRn;
    cudaGetSymbolAddress((void**)&gQ,  g_Q);
    cudaGetSymbolAddress((void**)&gK,  g_K);
    cudaGetSymbolAddress((void**)&gV,  g_V);
    cudaGetSymbolAddress((void**)&gA,  g_A);
    cudaGetSymbolAddress((void**)&gFn, g_Fn);
    cudaGetSymbolAddress((void**)&gRn, g_Rn);

    cudaFuncSetAttribute(attn_kernel,
                         cudaFuncAttributeMaxDynamicSharedMemorySize, SMEM_BYTES);

    // 1) normalize features / requirements
    l2norm_kernel<<<(2 * Bn * Sn) / 8, 256>>>(feat, req, gFn, gRn);

    // 2) Q/K/V projections (fused via gridDim.z)
    sgemm3<<<dim3(Dn / BN, Mrows / BM, 3), 256>>>(
        x, Wq, Wk, Wv, bq, bk, bv, gQ, gK, gV);

    // 3) causal flash attention with fused ASA bias
    attn_kernel<<<dim3(Sn / 64, Hn, Bn), 256, SMEM_BYTES>>>(
        gQ, gK, gV, gFn, gRn, gA);

    // 4) output projection -> d_out
    sgemm3<<<dim3(Dn / BN, Mrows / BM, 1), 256>>>(
        gA, Wo, Wo, Wo, bo, bo, bo, out, out, out);
}

// round 3
// speedup vs baseline: 3.7089x; 3.7089x over previous
#include <cuda_runtime.h>
#include <math.h>

#define Bn 2
#define Sn 2048
#define Dn 1024
#define Hn 16
#define DKn 64
#define FDn 64
#define Mrows (Bn*Sn)

// ---------------- scratch ----------------
__device__ float g_Q[Mrows * Dn];
__device__ float g_K[Mrows * Dn];
__device__ float g_V[Mrows * Dn];
__device__ float g_A[Mrows * Dn];
__device__ float g_Fn[Bn * Sn * FDn];
__device__ float g_Rn[Bn * Sn * FDn];

__device__ __forceinline__ unsigned f2tf(float x) {
    unsigned r; asm("cvt.rna.tf32.f32 %0, %1;" : "=r"(r) : "f"(x)); return r;
}
__device__ __forceinline__ void mma8(float* c, unsigned a0, unsigned a1,
                                     unsigned a2, unsigned a3,
                                     unsigned b0, unsigned b1) {
    asm volatile("mma.sync.aligned.m16n8k8.row.col.f32.tf32.tf32.f32 "
                 "{%0,%1,%2,%3}, {%4,%5,%6,%7}, {%8,%9}, {%0,%1,%2,%3};"
                 : "+f"(c[0]), "+f"(c[1]), "+f"(c[2]), "+f"(c[3])
                 : "r"(a0), "r"(a1), "r"(a2), "r"(a3), "r"(b0), "r"(b1));
}

// ---------------- l2 normalize ----------------
__global__ __launch_bounds__(256) void l2norm_kernel(
    const float* __restrict__ feat, const float* __restrict__ req,
    float* __restrict__ featn, float* __restrict__ reqn)
{
    int warp = (blockIdx.x * blockDim.x + threadIdx.x) >> 5;
    int lane = threadIdx.x & 31;
    if (warp >= 2 * Bn * Sn) return;
    const float* src; float* dst; int row;
    if (warp < Bn * Sn) { src = feat; dst = featn; row = warp; }
    else                { src = req;  dst = reqn;  row = warp - Bn * Sn; }
    float2 v = ((const float2*)src)[row * 32 + lane];
    float ss = v.x * v.x + v.y * v.y;
    #pragma unroll
    for (int o = 16; o; o >>= 1) ss += __shfl_xor_sync(0xffffffffu, ss, o);
    float inv = 1.0f / fmaxf(sqrtf(ss), 1e-12f);
    ((float2*)dst)[row * 32 + lane] = make_float2(v.x * inv, v.y * inv);
}

// ---------------- tf32 GEMM: C = A[4096,1024]*W[1024,1024] + bias ----------------
// 128x128 tile, BK=32, 8 warps (2x4), warp tile 64x32, m16n8k8 with k-perm.
#define AST 40
#define BST 132
__global__ __launch_bounds__(256, 2) void gemm_tf32(
    const float* __restrict__ A,
    const float* __restrict__ W0, const float* __restrict__ W1, const float* __restrict__ W2,
    const float* __restrict__ c0p, const float* __restrict__ c1p, const float* __restrict__ c2p,
    float* __restrict__ C0, float* __restrict__ C1, float* __restrict__ C2)
{
    const float* __restrict__ W    = (blockIdx.z == 0) ? W0 : (blockIdx.z == 1) ? W1 : W2;
    const float* __restrict__ bias = (blockIdx.z == 0) ? c0p : (blockIdx.z == 1) ? c1p : c2p;
    float* __restrict__ C          = (blockIdx.z == 0) ? C0 : (blockIdx.z == 1) ? C1 : C2;

    __shared__ unsigned As[128 * AST];
    __shared__ unsigned Bs[32 * BST];

    int tid = threadIdx.x, lane = tid & 31, warp = tid >> 5;
    int g = lane >> 2, t = lane & 3;
    int wm = warp >> 2, wn = warp & 3;
    int m0 = blockIdx.y * 128, n0 = blockIdx.x * 128;

    float acc[4][4][4];
    #pragma unroll
    for (int i = 0; i < 4; i++)
        #pragma unroll
        for (int j = 0; j < 4; j++)
            #pragma unroll
            for (int r = 0; r < 4; r++) acc[i][j][r] = 0.0f;

    int ar = tid >> 3, ac = (tid & 7) * 4;
    int br = tid >> 5, bc = (tid & 31) * 4;

    for (int k0 = 0; k0 < Dn; k0 += 32) {
        #pragma unroll
        for (int p = 0; p < 4; ++p) {
            float4 va = *(const float4*)&A[(size_t)(m0 + ar + 32 * p) * Dn + k0 + ac];
            *(uint4*)&As[(ar + 32 * p) * AST + ac] =
                make_uint4(f2tf(va.x), f2tf(va.y), f2tf(va.z), f2tf(va.w));
            float4 vb = *(const float4*)&W[(size_t)(k0 + br + 8 * p) * Dn + n0 + bc];
            *(uint4*)&Bs[(br + 8 * p) * BST + bc] =
                make_uint4(f2tf(vb.x), f2tf(vb.y), f2tf(vb.z), f2tf(vb.w));
        }
        __syncthreads();
        #pragma unroll
        for (int s = 0; s < 4; ++s) {
            int kb = s * 8 + 2 * t;
            unsigned a[4][4];
            #pragma unroll
            for (int mt = 0; mt < 4; ++mt) {
                int r = (wm * 64 + mt * 16 + g) * AST + kb;
                uint2 lo = *(const uint2*)&As[r];
                uint2 hi = *(const uint2*)&As[r + 8 * AST];
                a[mt][0] = lo.x; a[mt][1] = hi.x; a[mt][2] = lo.y; a[mt][3] = hi.y;
            }
            #pragma unroll
            for (int nt = 0; nt < 4; ++nt) {
                int col = wn * 32 + nt * 8 + g;
                unsigned q0 = Bs[kb * BST + col];
                unsigned q1 = Bs[(kb + 1) * BST + col];
                #pragma unroll
                for (int mt = 0; mt < 4; ++mt)
                    mma8(acc[mt][nt], a[mt][0], a[mt][1], a[mt][2], a[mt][3], q0, q1);
            }
        }
        __syncthreads();
    }

    #pragma unroll
    for (int mt = 0; mt < 4; ++mt) {
        int row = m0 + wm * 64 + mt * 16 + g;
        #pragma unroll
        for (int nt = 0; nt < 4; ++nt) {
            int col = n0 + wn * 32 + nt * 8 + 2 * t;
            float b0 = bias[col], b1 = bias[col + 1];
            *(float2*)&C[(size_t)row * Dn + col] =
                make_float2(acc[mt][nt][0] + b0, acc[mt][nt][1] + b1);
            *(float2*)&C[(size_t)(row + 8) * Dn + col] =
                make_float2(acc[mt][nt][2] + b0, acc[mt][nt][3] + b1);
        }
    }
}

// ---------------- tf32 flash attention, fused ASA bias ----------------
// q-tile 128 (8 warps x 16 rows), kv-tile 64. Qext=[Q/8|req_n], Kext=[K|feat_n].
// P stays in registers (C-frag == A-frag layout under the k-permutation).
#define QST 136
#define KST 136
#define VST 68
#define QS_SZ (128 * QST)
#define KS_SZ (64 * KST)
#define VS_SZ (64 * VST)
#define ATT_SMEM ((QS_SZ + KS_SZ + VS_SZ) * 4)   // 121856 B

__global__ __launch_bounds__(256) void attn_tf32(
    const float* __restrict__ Q, const float* __restrict__ K, const float* __restrict__ V,
    const float* __restrict__ featn, const float* __restrict__ reqn,
    float* __restrict__ O)
{
    extern __shared__ unsigned sm[];
    unsigned* Qs = sm;
    unsigned* Ks = sm + QS_SZ;
    unsigned* Vs = sm + QS_SZ + KS_SZ;

    int tid = threadIdx.x, lane = tid & 31, warp = tid >> 5;
    int g = lane >> 2, t = lane & 3;
    int qt = 15 - blockIdx.x;                 // biggest tiles first
    int h = blockIdx.y, b = blockIdx.z;
    int qbase = qt * 128, rowoff = b * Sn;
    int wq = warp * 16;

    // load Qext tile [128][128]
    for (int i = tid; i < 128 * 32; i += 256) {
        int r = i >> 5, d4 = i & 31;
        float4 v;
        if (d4 < 16) {
            v = *(const float4*)&Q[(size_t)(rowoff + qbase + r) * Dn + h * DKn + d4 * 4];
            v.x *= 0.125f; v.y *= 0.125f; v.z *= 0.125f; v.w *= 0.125f;
        } else {
            v = *(const float4*)&reqn[(size_t)(rowoff + qbase + r) * FDn + (d4 - 16) * 4];
        }
        *(uint4*)&Qs[r * QST + d4 * 4] = make_uint4(f2tf(v.x), f2tf(v.y), f2tf(v.z), f2tf(v.w));
    }

    float o[8][4];
    #pragma unroll
    for (int vt = 0; vt < 8; vt++)
        #pragma unroll
        for (int j = 0; j < 4; j++) o[vt][j] = 0.0f;
    float m0 = -1e30f, m1 = -1e30f, l0 = 0.0f, l1 = 0.0f;

    int rg0 = qbase + wq + g, rg1 = rg0 + 8;
    int jmax = 2 * qt + 1;

    for (int jt = 0; jt <= jmax; jt++) {
        int kb = jt * 64;
        __syncthreads();   // previous iter reads done (also covers Qs store)
        for (int i = tid; i < 64 * 32; i += 256) {
            int r = i >> 5, d4 = i & 31;
            float4 v;
            if (d4 < 16)
                v = *(const float4*)&K[(size_t)(rowoff + kb + r) * Dn + h * DKn + d4 * 4];
            else
                v = *(const float4*)&featn[(size_t)(rowoff + kb + r) * FDn + (d4 - 16) * 4];
            *(uint4*)&Ks[r * KST + d4 * 4] = make_uint4(f2tf(v.x), f2tf(v.y), f2tf(v.z), f2tf(v.w));
        }
        for (int i = tid; i < 64 * 16; i += 256) {
            int r = i >> 4, d4 = i & 15;
            float4 v = *(const float4*)&V[(size_t)(rowoff + kb + r) * Dn + h * DKn + d4 * 4];
            *(uint4*)&Vs[r * VST + d4 * 4] = make_uint4(f2tf(v.x), f2tf(v.y), f2tf(v.z), f2tf(v.w));
        }
        __syncthreads();

        // ---- S = Qext . Kext^T  (16x64 per warp) ----
        float s[8][4];
        #pragma unroll
        for (int nt = 0; nt < 8; nt++)
            #pragma unroll
            for (int j = 0; j < 4; j++) s[nt][j] = 0.0f;

        #pragma unroll
        for (int oct = 0; oct < 16; oct++) {
            int kk = oct * 8 + 2 * t;
            uint2 alo = *(const uint2*)&Qs[(wq + g) * QST + kk];
            uint2 ahi = *(const uint2*)&Qs[(wq + g + 8) * QST + kk];
            #pragma unroll
            for (int nt = 0; nt < 8; nt++) {
                uint2 bb = *(const uint2*)&Ks[(nt * 8 + g) * KST + kk];
                mma8(s[nt], alo.x, ahi.x, alo.y, ahi.y, bb.x, bb.y);
            }
        }

        // ---- causal mask ----
        if (kb + 63 > rg0) {
            #pragma unroll
            for (int nt = 0; nt < 8; nt++) {
                int c0 = kb + nt * 8 + 2 * t, c1 = c0 + 1;
                if (c0 > rg0) s[nt][0] = -1e30f;
                if (c1 > rg0) s[nt][1] = -1e30f;
                if (c0 > rg1) s[nt][2] = -1e30f;
                if (c1 > rg1) s[nt][3] = -1e30f;
            }
        }

        // ---- online softmax (rows g, g+8 within warp) ----
        float tm0 = -1e30f, tm1 = -1e30f;
        #pragma unroll
        for (int nt = 0; nt < 8; nt++) {
            tm0 = fmaxf(tm0, fmaxf(s[nt][0], s[nt][1]));
            tm1 = fmaxf(tm1, fmaxf(s[nt][2], s[nt][3]));
        }
        tm0 = fmaxf(tm0, __shfl_xor_sync(0xffffffffu, tm0, 1));
        tm0 = fmaxf(tm0, __shfl_xor_sync(0xffffffffu, tm0, 2));
        tm1 = fmaxf(tm1, __shfl_xor_sync(0xffffffffu, tm1, 1));
        tm1 = fmaxf(tm1, __shfl_xor_sync(0xffffffffu, tm1, 2));
        float mn0 = fmaxf(m0, tm0), mn1 = fmaxf(m1, tm1);
        float cr0 = __expf(m0 - mn0), cr1 = __expf(m1 - mn1);
        float rs0 = 0.0f, rs1 = 0.0f;
        #pragma unroll
        for (int nt = 0; nt < 8; nt++) {
            s[nt][0] = __expf(s[nt][0] - mn0);
            s[nt][1] = __expf(s[nt][1] - mn0);
            s[nt][2] = __expf(s[nt][2] - mn1);
            s[nt][3] = __expf(s[nt][3] - mn1);
            rs0 += s[nt][0] + s[nt][1];
            rs1 += s[nt][2] + s[nt][3];
        }
        rs0 += __shfl_xor_sync(0xffffffffu, rs0, 1);
        rs0 += __shfl_xor_sync(0xffffffffu, rs0, 2);
        rs1 += __shfl_xor_sync(0xffffffffu, rs1, 1);
        rs1 += __shfl_xor_sync(0xffffffffu, rs1, 2);
        l0 = l0 * cr0 + rs0; m0 = mn0;
        l1 = l1 * cr1 + rs1; m1 = mn1;
        #pragma unroll
        for (int vt = 0; vt < 8; vt++) {
            o[vt][0] *= cr0; o[vt][1] *= cr0;
            o[vt][2] *= cr1; o[vt][3] *= cr1;
        }

        // ---- P to tf32 (in place), then O += P . V ----
        #pragma unroll
        for (int nt = 0; nt < 8; nt++)
            #pragma unroll
            for (int j = 0; j < 4; j++)
                s[nt][j] = __uint_as_float(f2tf(s[nt][j]));

        #pragma unroll
        for (int oct = 0; oct < 8; oct++) {
            int kk = oct * 8 + 2 * t;
            unsigned pa0 = __float_as_uint(s[oct][0]);
            unsigned pa1 = __float_as_uint(s[oct][2]);
            unsigned pa2 = __float_as_uint(s[oct][1]);
            unsigned pa3 = __float_as_uint(s[oct][3]);
            #pragma unroll
            for (int vt = 0; vt < 8; vt++) {
                unsigned b0 = Vs[kk * VST + vt * 8 + g];
                unsigned b1 = Vs[(kk + 1) * VST + vt * 8 + g];
                mma8(o[vt], pa0, pa1, pa2, pa3, b0, b1);
            }
        }
    }

    // ---- epilogue ----
    float inv0 = 1.0f / l0, inv1 = 1.0f / l1;
    int r0 = rowoff + rg0, r1 = rowoff + rg1;
    #pragma unroll
    for (int vt = 0; vt < 8; vt++) {
        int col = h * DKn + vt * 8 + 2 * t;
        *(float2*)&O[(size_t)r0 * Dn + col] = make_float2(o[vt][0] * inv0, o[vt][1] * inv0);
        *(float2*)&O[(size_t)r1 * Dn + col] = make_float2(o[vt][2] * inv1, o[vt][3] * inv1);
    }
}

// ---------------- launch ----------------
extern "C" void kernel_launch(void* const* d_in, const int* in_sizes, int n_in,
                              void* d_out, int out_size)
{
    const float* x    = (const float*)d_in[0];
    const float* feat = (const float*)d_in[1];
    const float* req  = (const float*)d_in[2];
    const float* Wq   = (const float*)d_in[3];
    const float* bq   = (const float*)d_in[4];
    const float* Wk   = (const float*)d_in[5];
    const float* bk   = (const float*)d_in[6];
    const float* Wv   = (const float*)d_in[7];
    const float* bv   = (const float*)d_in[8];
    const float* Wo   = (const float*)d_in[9];
    const float* bo   = (const float*)d_in[10];
    float* out = (float*)d_out;

    float *gQ, *gK, *gV, *gA, *gFn, *gRn;
    cudaGetSymbolAddress((void**)&gQ,  g_Q);
    cudaGetSymbolAddress((void**)&gK,  g_K);
    cudaGetSymbolAddress((void**)&gV,  g_V);
    cudaGetSymbolAddress((void**)&gA,  g_A);
    cudaGetSymbolAddress((void**)&gFn, g_Fn);
    cudaGetSymbolAddress((void**)&gRn, g_Rn);

    cudaFuncSetAttribute(attn_tf32,
                         cudaFuncAttributeMaxDynamicSharedMemorySize, ATT_SMEM);

    l2norm_kernel<<<(2 * Bn * Sn) / 8, 256>>>(feat, req, gFn, gRn);

    gemm_tf32<<<dim3(Dn / 128, Mrows / 128, 3), 256>>>(
        x, Wq, Wk, Wv, bq, bk, bv, gQ, gK, gV);

    attn_tf32<<<dim3(16, Hn, Bn), 256, ATT_SMEM>>>(gQ, gK, gV, gFn, gRn, gA);

    gemm_tf32<<<dim3(Dn / 128, Mrows / 128, 1), 256>>>(
        gA, Wo, Wo, Wo, bo, bo, bo, out, out, out);
}

// round 4
// speedup vs baseline: 5.0196x; 1.3534x over previous
#include <cuda_runtime.h>
#include <math.h>

#define Bn 2
#define Sn 2048
#define Dn 1024
#define Hn 16
#define DKn 64
#define FDn 64
#define Mrows (Bn*Sn)

// ---------------- scratch ----------------
__device__ float g_Q[Mrows * Dn];
__device__ float g_K[Mrows * Dn];
__device__ float g_V[Mrows * Dn];
__device__ float g_A[Mrows * Dn];
__device__ float g_X[Mrows * Dn];        // x rounded to tf32
__device__ float g_Wr[4][Dn * Dn];       // Wq,Wk,Wv,Wo rounded
__device__ float g_Fn[Bn * Sn * FDn];
__device__ float g_Rn[Bn * Sn * FDn];

__device__ __forceinline__ unsigned f2tf(float x) {
    unsigned r; asm("cvt.rna.tf32.f32 %0, %1;" : "=r"(r) : "f"(x)); return r;
}
__device__ __forceinline__ float ex2(float x) {
    float r; asm("ex2.approx.f32 %0, %1;" : "=f"(r) : "f"(x)); return r;
}
__device__ __forceinline__ void mma8(float* c, unsigned a0, unsigned a1,
                                     unsigned a2, unsigned a3,
                                     unsigned b0, unsigned b1) {
    asm volatile("mma.sync.aligned.m16n8k8.row.col.f32.tf32.tf32.f32 "
                 "{%0,%1,%2,%3}, {%4,%5,%6,%7}, {%8,%9}, {%0,%1,%2,%3};"
                 : "+f"(c[0]), "+f"(c[1]), "+f"(c[2]), "+f"(c[3])
                 : "r"(a0), "r"(a1), "r"(a2), "r"(a3), "r"(b0), "r"(b1));
}
__device__ __forceinline__ void cp16(unsigned dst, const void* src) {
    asm volatile("cp.async.cg.shared.global [%0], [%1], 16;" :: "r"(dst), "l"(src));
}

// ---------------- pre-round x + weights to tf32 ----------------
__global__ __launch_bounds__(256) void round_inputs(
    const float* __restrict__ x,
    const float* __restrict__ Wq, const float* __restrict__ Wk,
    const float* __restrict__ Wv, const float* __restrict__ Wo)
{
    int idx = blockIdx.x * 256 + threadIdx.x;   // float4 index
    const float* s; float* d; int off;
    if (idx < 1048576) { s = x; d = g_X; off = idx; }
    else {
        int j = idx - 1048576;
        int w = j >> 18;  off = j & 262143;
        s = (w == 0) ? Wq : (w == 1) ? Wk : (w == 2) ? Wv : Wo;
        d = g_Wr[w];
    }
    float4 v = ((const float4*)s)[off];
    ((uint4*)d)[off] = make_uint4(f2tf(v.x), f2tf(v.y), f2tf(v.z), f2tf(v.w));
}

// ---------------- l2 normalize (rounded output) ----------------
__global__ __launch_bounds__(256) void l2norm_kernel(
    const float* __restrict__ feat, const float* __restrict__ req,
    float* __restrict__ featn, float* __restrict__ reqn)
{
    int warp = (blockIdx.x * blockDim.x + threadIdx.x) >> 5;
    int lane = threadIdx.x & 31;
    if (warp >= 2 * Bn * Sn) return;
    const float* src; float* dst; int row;
    if (warp < Bn * Sn) { src = feat; dst = featn; row = warp; }
    else                { src = req;  dst = reqn;  row = warp - Bn * Sn; }
    float2 v = ((const float2*)src)[row * 32 + lane];
    float ss = v.x * v.x + v.y * v.y;
    #pragma unroll
    for (int o = 16; o; o >>= 1) ss += __shfl_xor_sync(0xffffffffu, ss, o);
    float inv = 1.0f / fmaxf(sqrtf(ss), 1e-12f);
    ((uint2*)dst)[row * 32 + lane] = make_uint2(f2tf(v.x * inv), f2tf(v.y * inv));
}

// ---------------- tf32 GEMM, cp.async double-buffered ----------------
#define AST 40
#define BST 132
#define STAGE_A (128 * AST)               // 5120 u32
#define STAGE_B (32 * BST)                // 4224 u32
#define GSTAGE (STAGE_A + STAGE_B)        // 9344 u32
#define GEMM_SMEM (2 * GSTAGE * 4)        // 74752 B

#define GEMM_CPA(stage, k0) do {                                              \
    unsigned as0 = sbase + (stage) * (GSTAGE * 4);                            \
    unsigned bs0 = as0 + STAGE_A * 4;                                         \
    _Pragma("unroll")                                                         \
    for (int p = 0; p < 4; p++) { int c = tid + 256 * p;                      \
        int r = c >> 3, q = (c & 7) * 4;                                      \
        cp16(as0 + (r * AST + q) * 4, &A[(size_t)(m0 + r) * Dn + (k0) + q]); }\
    _Pragma("unroll")                                                         \
    for (int p = 0; p < 4; p++) { int c = tid + 256 * p;                      \
        int r = c >> 5, q = (c & 31) * 4;                                     \
        cp16(bs0 + (r * BST + q) * 4, &W[(size_t)((k0) + r) * Dn + n0 + q]); }\
    asm volatile("cp.async.commit_group;");                                   \
} while (0)

__global__ __launch_bounds__(256, 2) void gemm_tf32(
    const float* __restrict__ A,
    const float* __restrict__ W0, const float* __restrict__ W1, const float* __restrict__ W2,
    const float* __restrict__ c0p, const float* __restrict__ c1p, const float* __restrict__ c2p,
    float* __restrict__ C0, float* __restrict__ C1, float* __restrict__ C2,
    int roundC)
{
    const float* __restrict__ W    = (blockIdx.z == 0) ? W0 : (blockIdx.z == 1) ? W1 : W2;
    const float* __restrict__ bias = (blockIdx.z == 0) ? c0p : (blockIdx.z == 1) ? c1p : c2p;
    float* __restrict__ C          = (blockIdx.z == 0) ? C0 : (blockIdx.z == 1) ? C1 : C2;

    extern __shared__ unsigned gsm[];
    unsigned sbase = (unsigned)__cvta_generic_to_shared(gsm);

    int tid = threadIdx.x, lane = tid & 31, warp = tid >> 5;
    int g = lane >> 2, t = lane & 3;
    int wm = warp >> 2, wn = warp & 3;
    int m0 = blockIdx.y * 128, n0 = blockIdx.x * 128;

    float acc[4][4][4];
    #pragma unroll
    for (int i = 0; i < 4; i++)
        #pragma unroll
        for (int j = 0; j < 4; j++)
            #pragma unroll
            for (int r = 0; r < 4; r++) acc[i][j][r] = 0.0f;

    GEMM_CPA(0, 0);

    for (int it = 0; it < 32; ++it) {
        int cur = it & 1;
        if (it < 31) {
            GEMM_CPA(cur ^ 1, (it + 1) * 32);
            asm volatile("cp.async.wait_group 1;");
        } else {
            asm volatile("cp.async.wait_group 0;");
        }
        __syncthreads();

        unsigned* Asb = gsm + cur * GSTAGE;
        unsigned* Bsb = Asb + STAGE_A;
        #pragma unroll
        for (int s = 0; s < 4; ++s) {
            int kb = s * 8 + 2 * t;
            unsigned a[4][4];
            #pragma unroll
            for (int mt = 0; mt < 4; ++mt) {
                int r = (wm * 64 + mt * 16 + g) * AST + kb;
                uint2 lo = *(const uint2*)&Asb[r];
                uint2 hi = *(const uint2*)&Asb[r + 8 * AST];
                a[mt][0] = lo.x; a[mt][1] = hi.x; a[mt][2] = lo.y; a[mt][3] = hi.y;
            }
            #pragma unroll
            for (int nt = 0; nt < 4; ++nt) {
                int col = wn * 32 + nt * 8 + g;
                unsigned q0 = Bsb[kb * BST + col];
                unsigned q1 = Bsb[(kb + 1) * BST + col];
                #pragma unroll
                for (int mt = 0; mt < 4; ++mt)
                    mma8(acc[mt][nt], a[mt][0], a[mt][1], a[mt][2], a[mt][3], q0, q1);
            }
        }
        __syncthreads();
    }

    #pragma unroll
    for (int mt = 0; mt < 4; ++mt) {
        int row = m0 + wm * 64 + mt * 16 + g;
        #pragma unroll
        for (int nt = 0; nt < 4; ++nt) {
            int col = n0 + wn * 32 + nt * 8 + 2 * t;
            float b0 = bias[col], b1 = bias[col + 1];
            float x0 = acc[mt][nt][0] + b0, x1 = acc[mt][nt][1] + b1;
            float x2 = acc[mt][nt][2] + b0, x3 = acc[mt][nt][3] + b1;
            if (roundC) {
                x0 = __uint_as_float(f2tf(x0)); x1 = __uint_as_float(f2tf(x1));
                x2 = __uint_as_float(f2tf(x2)); x3 = __uint_as_float(f2tf(x3));
            }
            *(float2*)&C[(size_t)row * Dn + col]       = make_float2(x0, x1);
            *(float2*)&C[(size_t)(row + 8) * Dn + col] = make_float2(x2, x3);
        }
    }
}

// ---------------- tf32 flash attention, cp.async double-buffered KV ----------------
#define QST 136
#define KST 136
#define VST 68
#define QS_SZ (128 * QST)                 // 17408 u32
#define KS_SZ (64 * KST)                  // 8704
#define VS_SZ (64 * VST)                  // 4352
#define KV_SZ (KS_SZ + VS_SZ)             // 13056
#define ATT_SMEM ((QS_SZ + 2 * KV_SZ) * 4)  // 174080 B

#define ISSUE_KV(stage, kb) do {                                               \
    unsigned ks0 = abase + (QS_SZ + (stage) * KV_SZ) * 4;                      \
    unsigned vs0 = ks0 + KS_SZ * 4;                                            \
    _Pragma("unroll")                                                          \
    for (int p = 0; p < 8; p++) { int c = tid + 256 * p;                       \
        int r = c >> 5, d4 = c & 31;                                           \
        const float* src = (d4 < 16)                                           \
            ? &Kp[(size_t)(rowoff + (kb) + r) * Dn + h * DKn + d4 * 4]         \
            : &Fp[(size_t)(rowoff + (kb) + r) * FDn + (d4 - 16) * 4];          \
        cp16(ks0 + (r * KST + d4 * 4) * 4, src); }                             \
    _Pragma("unroll")                                                          \
    for (int p = 0; p < 4; p++) { int c = tid + 256 * p;                       \
        int r = c >> 4, d4 = c & 15;                                           \
        cp16(vs0 + (r * VST + d4 * 4) * 4,                                     \
             &Vp[(size_t)(rowoff + (kb) + r) * Dn + h * DKn + d4 * 4]); }      \
    asm volatile("cp.async.commit_group;");                                    \
} while (0)

__global__ __launch_bounds__(256) void attn_tf32(
    const float* __restrict__ Qp, const float* __restrict__ Kp, const float* __restrict__ Vp,
    const float* __restrict__ Fp, const float* __restrict__ Rp,
    float* __restrict__ O)
{
    extern __shared__ unsigned sm[];
    unsigned abase = (unsigned)__cvta_generic_to_shared(sm);
    unsigned* Qs = sm;

    int tid = threadIdx.x, lane = tid & 31, warp = tid >> 5;
    int g = lane >> 2, t = lane & 3;
    int qt = 15 - blockIdx.x;
    int h = blockIdx.y, b = blockIdx.z;
    int qbase = qt * 128, rowoff = b * Sn;
    int wq = warp * 16;

    const float L2E = 1.4426950408889634f;
    // Qext = [log2e/8 * Q | log2e * req_n], rounded to tf32
    for (int i = tid; i < 128 * 32; i += 256) {
        int r = i >> 5, d4 = i & 31;
        float4 v; float sc;
        if (d4 < 16) {
            v = *(const float4*)&Qp[(size_t)(rowoff + qbase + r) * Dn + h * DKn + d4 * 4];
            sc = L2E * 0.125f;
        } else {
            v = *(const float4*)&Rp[(size_t)(rowoff + qbase + r) * FDn + (d4 - 16) * 4];
            sc = L2E;
        }
        *(uint4*)&Qs[r * QST + d4 * 4] =
            make_uint4(f2tf(v.x * sc), f2tf(v.y * sc), f2tf(v.z * sc), f2tf(v.w * sc));
    }

    float o[8][4];
    #pragma unroll
    for (int vt = 0; vt < 8; vt++)
        #pragma unroll
        for (int j = 0; j < 4; j++) o[vt][j] = 0.0f;
    float m0 = -1e30f, m1 = -1e30f, l0 = 0.0f, l1 = 0.0f;

    int rg0 = qbase + wq + g, rg1 = rg0 + 8;
    int jmax = 2 * qt + 1;

    ISSUE_KV(0, 0);

    for (int jt = 0; jt <= jmax; jt++) {
        int cur = jt & 1;
        if (jt < jmax) {
            ISSUE_KV(cur ^ 1, (jt + 1) * 64);
            asm volatile("cp.async.wait_group 1;");
        } else {
            asm volatile("cp.async.wait_group 0;");
        }
        __syncthreads();

        unsigned* Ks = sm + QS_SZ + cur * KV_SZ;
        unsigned* Vs = Ks + KS_SZ;
        int kb = jt * 64;

        // ---- S = Qext . Kext^T ----
        float s[8][4];
        #pragma unroll
        for (int nt = 0; nt < 8; nt++)
            #pragma unroll
            for (int j = 0; j < 4; j++) s[nt][j] = 0.0f;

        #pragma unroll
        for (int oct = 0; oct < 16; oct++) {
            int kk = oct * 8 + 2 * t;
            uint2 alo = *(const uint2*)&Qs[(wq + g) * QST + kk];
            uint2 ahi = *(const uint2*)&Qs[(wq + g + 8) * QST + kk];
            #pragma unroll
            for (int nt = 0; nt < 8; nt++) {
                uint2 bb = *(const uint2*)&Ks[(nt * 8 + g) * KST + kk];
                mma8(s[nt], alo.x, ahi.x, alo.y, ahi.y, bb.x, bb.y);
            }
        }

        // ---- causal mask ----
        if (kb + 63 > rg0) {
            #pragma unroll
            for (int nt = 0; nt < 8; nt++) {
                int c0 = kb + nt * 8 + 2 * t, c1 = c0 + 1;
                if (c0 > rg0) s[nt][0] = -1e30f;
                if (c1 > rg0) s[nt][1] = -1e30f;
                if (c0 > rg1) s[nt][2] = -1e30f;
                if (c1 > rg1) s[nt][3] = -1e30f;
            }
        }

        // ---- online softmax (base-2) ----
        float tm0 = -1e30f, tm1 = -1e30f;
        #pragma unroll
        for (int nt = 0; nt < 8; nt++) {
            tm0 = fmaxf(tm0, fmaxf(s[nt][0], s[nt][1]));
            tm1 = fmaxf(tm1, fmaxf(s[nt][2], s[nt][3]));
        }
        tm0 = fmaxf(tm0, __shfl_xor_sync(0xffffffffu, tm0, 1));
        tm0 = fmaxf(tm0, __shfl_xor_sync(0xffffffffu, tm0, 2));
        tm1 = fmaxf(tm1, __shfl_xor_sync(0xffffffffu, tm1, 1));
        tm1 = fmaxf(tm1, __shfl_xor_sync(0xffffffffu, tm1, 2));
        float mn0 = fmaxf(m0, tm0), mn1 = fmaxf(m1, tm1);
        float cr0 = ex2(m0 - mn0), cr1 = ex2(m1 - mn1);
        float rs0 = 0.0f, rs1 = 0.0f;
        #pragma unroll
        for (int nt = 0; nt < 8; nt++) {
            s[nt][0] = ex2(s[nt][0] - mn0);
            s[nt][1] = ex2(s[nt][1] - mn0);
            s[nt][2] = ex2(s[nt][2] - mn1);
            s[nt][3] = ex2(s[nt][3] - mn1);
            rs0 += s[nt][0] + s[nt][1];
            rs1 += s[nt][2] + s[nt][3];
        }
        rs0 += __shfl_xor_sync(0xffffffffu, rs0, 1);
        rs0 += __shfl_xor_sync(0xffffffffu, rs0, 2);
        rs1 += __shfl_xor_sync(0xffffffffu, rs1, 1);
        rs1 += __shfl_xor_sync(0xffffffffu, rs1, 2);
        l0 = l0 * cr0 + rs0; m0 = mn0;
        l1 = l1 * cr1 + rs1; m1 = mn1;
        #pragma unroll
        for (int vt = 0; vt < 8; vt++) {
            o[vt][0] *= cr0; o[vt][1] *= cr0;
            o[vt][2] *= cr1; o[vt][3] *= cr1;
        }

        // ---- P -> tf32, O += P . V ----
        #pragma unroll
        for (int nt = 0; nt < 8; nt++)
            #pragma unroll
            for (int j = 0; j < 4; j++)
                s[nt][j] = __uint_as_float(f2tf(s[nt][j]));

        #pragma unroll
        for (int oct = 0; oct < 8; oct++) {
            int kk = oct * 8 + 2 * t;
            unsigned pa0 = __float_as_uint(s[oct][0]);
            unsigned pa1 = __float_as_uint(s[oct][2]);
            unsigned pa2 = __float_as_uint(s[oct][1]);
            unsigned pa3 = __float_as_uint(s[oct][3]);
            #pragma unroll
            for (int vt = 0; vt < 8; vt++) {
                unsigned b0 = Vs[kk * VST + vt * 8 + g];
                unsigned b1 = Vs[(kk + 1) * VST + vt * 8 + g];
                mma8(o[vt], pa0, pa1, pa2, pa3, b0, b1);
            }
        }
        __syncthreads();
    }

    // ---- epilogue (rounded: feeds final tf32 GEMM) ----
    float inv0 = 1.0f / l0, inv1 = 1.0f / l1;
    int r0 = rowoff + rg0, r1 = rowoff + rg1;
    #pragma unroll
    for (int vt = 0; vt < 8; vt++) {
        int col = h * DKn + vt * 8 + 2 * t;
        *(uint2*)&O[(size_t)r0 * Dn + col] =
            make_uint2(f2tf(o[vt][0] * inv0), f2tf(o[vt][1] * inv0));
        *(uint2*)&O[(size_t)r1 * Dn + col] =
            make_uint2(f2tf(o[vt][2] * inv1), f2tf(o[vt][3] * inv1));
    }
}

// ---------------- launch ----------------
extern "C" void kernel_launch(void* const* d_in, const int* in_sizes, int n_in,
                              void* d_out, int out_size)
{
    const float* x    = (const float*)d_in[0];
    const float* feat = (const float*)d_in[1];
    const float* req  = (const float*)d_in[2];
    const float* Wq   = (const float*)d_in[3];
    const float* bq   = (const float*)d_in[4];
    const float* Wk   = (const float*)d_in[5];
    const float* bk   = (const float*)d_in[6];
    const float* Wv   = (const float*)d_in[7];
    const float* bv   = (const float*)d_in[8];
    const float* Wo   = (const float*)d_in[9];
    const float* bo   = (const float*)d_in[10];
    float* out = (float*)d_out;

    float *gQ, *gK, *gV, *gA, *gX, *gW, *gFn, *gRn;
    cudaGetSymbolAddress((void**)&gQ,  g_Q);
    cudaGetSymbolAddress((void**)&gK,  g_K);
    cudaGetSymbolAddress((void**)&gV,  g_V);
    cudaGetSymbolAddress((void**)&gA,  g_A);
    cudaGetSymbolAddress((void**)&gX,  g_X);
    cudaGetSymbolAddress((void**)&gW,  g_Wr);
    cudaGetSymbolAddress((void**)&gFn, g_Fn);
    cudaGetSymbolAddress((void**)&gRn, g_Rn);
    const float* gWq = gW;
    const float* gWk = gW + Dn * Dn;
    const float* gWv = gW + 2 * Dn * Dn;
    const float* gWo = gW + 3 * Dn * Dn;

    cudaFuncSetAttribute(gemm_tf32,
                         cudaFuncAttributeMaxDynamicSharedMemorySize, GEMM_SMEM);
    cudaFuncSetAttribute(attn_tf32,
                         cudaFuncAttributeMaxDynamicSharedMemorySize, ATT_SMEM);

    round_inputs<<<8192, 256>>>(x, Wq, Wk, Wv, Wo);
    l2norm_kernel<<<(2 * Bn * Sn) / 8, 256>>>(feat, req, gFn, gRn);

    gemm_tf32<<<dim3(8, 32, 3), 256, GEMM_SMEM>>>(
        gX, gWq, gWk, gWv, bq, bk, bv, gQ, gK, gV, 1);

    attn_tf32<<<dim3(16, Hn, Bn), 256, ATT_SMEM>>>(gQ, gK, gV, gFn, gRn, gA);

    gemm_tf32<<<dim3(8, 32, 1), 256, GEMM_SMEM>>>(
        gA, gWo, gWo, gWo, bo, bo, bo, out, out, out, 0);
}